// round 4
// baseline (speedup 1.0000x reference)
#include <cuda_runtime.h>

#define NN 400
#define FF 240
#define CC 32
#define LL 1440
#define NK 304
#define SIN_X2 480   // row index of swE in sw; swEt at 481

// ---- scratch (device globals; no allocation allowed) ----
__device__ float g_Xi[NN * CC];
__device__ float g_Xj[NN * CC];
__device__ float g_aggI[NN * CC];
__device__ float g_aggJ[NN * CC];
__device__ float g_e1[NN * NN];
__device__ float g_e1T[NN * NN];
__device__ float g_aT[NN * NN];
__device__ float g_eT[NN * NN];
__device__ float g_x1[NN * FF];
__device__ float g_x2[NN * FF];

// ============================================================
// K0: transpose a -> g_aT, e -> g_eT (32x32 tiles, 256 thr)
// ============================================================
__global__ void __launch_bounds__(256) prep_kernel(
    const float* __restrict__ a, const float* __restrict__ e)
{
    __shared__ float t[32][33];
    const float* src = blockIdx.y ? e : a;
    float* dst = blockIdx.y ? g_eT : g_aT;
    int bx = blockIdx.x % 13, by = blockIdx.x / 13;
    int x0 = bx * 32, y0 = by * 32;
    int tx = threadIdx.x & 31, ty = threadIdx.x >> 5;
#pragma unroll
    for (int r = 0; r < 32; r += 8) {
        int y = y0 + ty + r, x = x0 + tx;
        if (y < NN && x < NN) t[ty + r][tx] = src[y * NN + x];
    }
    __syncthreads();
#pragma unroll
    for (int r = 0; r < 32; r += 8) {
        int y = x0 + ty + r, x = y0 + tx;
        if (y < NN && x < NN) dst[y * NN + x] = t[tx][ty + r];
    }
}

// ============================================================
// K1: Xi = x @ sw[0:F] + sb,  Xj = x @ sw[F:2F]
// 1024 threads: tid>>8 = K-quarter (60 each)
// ============================================================
__global__ void __launch_bounds__(1024) xw_kernel(
    const float* __restrict__ xin, const float* __restrict__ sw,
    const float* __restrict__ sb, int useX1)
{
    const float* x = useX1 ? g_x1 : xin;
    __shared__ __align__(16) float sx[4][FF];
    __shared__ float part[4][8][CC];
    int row0 = blockIdx.x * 4;
    int tid = threadIdx.x;
    for (int idx = tid; idx < 4 * FF; idx += 1024)
        sx[idx / FF][idx % FF] = x[row0 * FF + idx];
    __syncthreads();

    int kq = tid >> 8;
    int t2 = tid & 255;
    int w = t2 >> 5, c = t2 & 31;
    int r = w & 3;
    bool isJ = (w >= 4);
    const float* wb = sw + (isJ ? FF * CC : 0) + c + kq * 60 * CC;
    float a0 = 0.f, a1 = 0.f, a2 = 0.f, a3 = 0.f;
    const float4* sxr = (const float4*)sx[r] + kq * 15;
#pragma unroll
    for (int f4 = 0; f4 < 15; f4++) {
        float4 xv = sxr[f4];
        int f = f4 * 4;
        a0 += xv.x * __ldg(wb + (f + 0) * CC);
        a1 += xv.y * __ldg(wb + (f + 1) * CC);
        a2 += xv.z * __ldg(wb + (f + 2) * CC);
        a3 += xv.w * __ldg(wb + (f + 3) * CC);
    }
    part[kq][w][c] = (a0 + a1) + (a2 + a3);
    __syncthreads();
    if (kq == 0) {
        float v = (part[0][w][c] + part[1][w][c]) + (part[2][w][c] + part[3][w][c]);
        if (!isJ) v += sb[c];
        (isJ ? g_Xj : g_Xi)[(row0 + r) * CC + c] = v;
    }
}

// ============================================================
// K2: per-pair kernel, templated on LAYER.
// Layer 2 skips the edge-output dot entirely (~20% of hot loop).
// ============================================================
template <int LAYER>
__global__ void __launch_bounds__(128) pair_kernel(
    const float* __restrict__ eParam, const float* __restrict__ a,
    const float* __restrict__ sw,
    const float* __restrict__ aiw, const float* __restrict__ aib,
    const float* __restrict__ ajw, const float* __restrict__ ajb,
    const float* __restrict__ ew,  const float* __restrict__ eb)
{
    const float* e  = (LAYER == 2) ? g_e1  : eParam;
    const float* eT = (LAYER == 2) ? g_e1T : g_eT;
    bool colMode = (blockIdx.x >= NN);
    int fixed = colMode ? (blockIdx.x - NN) : blockIdx.x;

    const float* pA   = (colMode ? eT : e)  + fixed * NN;
    const float* pB   = (colMode ? e  : eT) + fixed * NN;
    const float* pAdj = (colMode ? g_aT : a) + fixed * NN;
    const float* pX   = colMode ? g_Xi : g_Xj;

    __shared__ __align__(16) float4 q[CC];  // (fixVec, swE, swEt, gateW)
    __shared__ float sEw[CC];
    __shared__ float sAcc[128][CC + 1];
    __shared__ float sPart[4][CC];

    int tid = threadIdx.x;
    if (tid < CC) {
        float fx = colMode ? g_Xj[fixed * CC + tid] : g_Xi[fixed * CC + tid];
        float gw = colMode ? ajw[tid] : aiw[tid];
        q[tid] = make_float4(fx, sw[SIN_X2 * CC + tid], sw[(SIN_X2 + 1) * CC + tid], gw);
        if (LAYER == 1) sEw[tid] = ew[tid];
    }
    __syncthreads();

    float gb  = colMode ? ajb[0] : aib[0];
    float ebv = (LAYER == 1) ? eb[0] : 0.f;
    float* eOut = (colMode ? g_e1T : g_e1) + fixed * NN;

    float acc[CC];
#pragma unroll
    for (int c = 0; c < CC; c++) acc[c] = 0.f;

    for (int v = tid; v < NN; v += 128) {
        float eij = __ldg(pA + v);
        float eji = __ldg(pB + v);
        float av  = __ldg(pAdj + v);
        const float4* vr = (const float4*)(pX + v * CC);

        float s = 0.f, se = 0.f;
        float tv[CC];
#pragma unroll
        for (int c4 = 0; c4 < CC / 4; c4++) {
            float4 vv = vr[c4];
            float vvals[4] = {vv.x, vv.y, vv.z, vv.w};
#pragma unroll
            for (int u = 0; u < 4; u++) {
                int c = c4 * 4 + u;
                float4 qq = q[c];
                float t = qq.x + vvals[u] + eij * qq.y + eji * qq.z;
                t = fmaxf(t, 0.f) * av;
                tv[c] = t;
                s += t * qq.w;
                if (LAYER == 1) se += t * sEw[c];
            }
        }
        float gate = 1.f / (1.f + __expf(-(s + gb)));
#pragma unroll
        for (int c = 0; c < CC; c++) acc[c] += gate * tv[c];
        if (LAYER == 1) eOut[v] = se + ebv;
    }

#pragma unroll
    for (int c = 0; c < CC; c++) sAcc[tid][c] = acc[c];
    __syncthreads();
    {
        int w = tid >> 5, c = tid & 31;
        float p = 0.f;
#pragma unroll
        for (int k = 0; k < 32; k++) p += sAcc[w * 32 + k][c];
        sPart[w][c] = p;
    }
    __syncthreads();
    if (tid < CC) {
        float r = (sPart[0][tid] + sPart[1][tid]) + (sPart[2][tid] + sPart[3][tid]);
        (colMode ? g_aggJ : g_aggI)[fixed * CC + tid] = r;
    }
}

// ============================================================
// K3: node model  x_out = [x, aggI, aggJ] @ nw + nb  (K=304)
// 512 thr = 4 K-quarters(76) x 128 (120 active colgroups x 2 cols).
// Weights stream as coalesced LDG.64; activations via smem broadcast.
// 4 rows/block, grid 100.
// ============================================================
#define NKQ 76
__global__ void __launch_bounds__(512) node_kernel(
    const float* __restrict__ xin, const float* __restrict__ nw,
    const float* __restrict__ nb, int layer)
{
    const float* x = (layer == 1) ? xin : g_x1;
    float* xout = (layer == 1) ? g_x1 : g_x2;
    __shared__ float s[4][NK];
    __shared__ float part[4][4][FF];
    int row0 = blockIdx.x * 4;
    int tid = threadIdx.x;
    for (int idx = tid; idx < 4 * NK; idx += 512) {
        int r = idx / NK, k = idx % NK;
        float v;
        if (k < FF)            v = x[(row0 + r) * FF + k];
        else if (k < FF + CC)  v = g_aggI[(row0 + r) * CC + (k - FF)];
        else                   v = g_aggJ[(row0 + r) * CC + (k - FF - CC)];
        s[r][k] = v;
    }
    __syncthreads();

    int kq = tid >> 7, cg = tid & 127;
    if (cg < 120) {
        int f0 = cg * 2;
        const float* wp = nw + f0;
        int kbase = kq * NKQ;
        float2 a0 = {0.f, 0.f}, a1 = {0.f, 0.f}, a2 = {0.f, 0.f}, a3 = {0.f, 0.f};
#pragma unroll 4
        for (int kk = 0; kk < NKQ; kk++) {
            int k = kbase + kk;
            float2 w = *(const float2*)(wp + k * FF);
            float x0 = s[0][k], x1 = s[1][k], x2 = s[2][k], x3 = s[3][k];
            a0.x += x0 * w.x; a0.y += x0 * w.y;
            a1.x += x1 * w.x; a1.y += x1 * w.y;
            a2.x += x2 * w.x; a2.y += x2 * w.y;
            a3.x += x3 * w.x; a3.y += x3 * w.y;
        }
        *(float2*)&part[kq][0][f0] = a0;
        *(float2*)&part[kq][1][f0] = a1;
        *(float2*)&part[kq][2][f0] = a2;
        *(float2*)&part[kq][3][f0] = a3;
    }
    __syncthreads();
    for (int idx = tid; idx < 4 * FF; idx += 512) {
        int r = idx / FF, f = idx % FF;
        float v = (part[0][r][f] + part[1][r][f]) +
                  (part[2][r][f] + part[3][r][f]) + nb[f];
        xout[(row0 + r) * FF + f] = v;
    }
}

// ============================================================
// K4: out = x2 @ dw + db   (400 x 1440, K=240)
// 256 thr = 4 K-quarters(60) x 64 (60 active colgroups x 4 cols).
// 8 rows x 240 cols per block; grid (6, 50).
// ============================================================
__global__ void __launch_bounds__(256) out_kernel(
    const float* __restrict__ dw, const float* __restrict__ db,
    float* __restrict__ out)
{
    __shared__ float s[8][FF];
    __shared__ float part[3][8][240];
    int tid = threadIdx.x;
    int row0 = blockIdx.y * 8;
    int colbase = blockIdx.x * 240;
    for (int idx = tid; idx < 8 * FF; idx += 256)
        s[idx / FF][idx % FF] = g_x2[row0 * FF + idx];
    __syncthreads();

    int kq = tid >> 6, cg = tid & 63;
    float4 acc[8];
#pragma unroll
    for (int r = 0; r < 8; r++) acc[r] = make_float4(0.f, 0.f, 0.f, 0.f);

    if (cg < 60) {
        const float* wp = dw + colbase + cg * 4;
        int kbase = kq * 60;
#pragma unroll 4
        for (int kk = 0; kk < 60; kk++) {
            int k = kbase + kk;
            float4 w = *(const float4*)(wp + k * LL);
#pragma unroll
            for (int r = 0; r < 8; r++) {
                float xr = s[r][k];
                acc[r].x += xr * w.x;
                acc[r].y += xr * w.y;
                acc[r].z += xr * w.z;
                acc[r].w += xr * w.w;
            }
        }
        if (kq > 0) {
#pragma unroll
            for (int r = 0; r < 8; r++)
                *(float4*)&part[kq - 1][r][cg * 4] = acc[r];
        }
    }
    __syncthreads();
    if (kq == 0 && cg < 60) {
        float4 bv = *(const float4*)(db + colbase + cg * 4);
#pragma unroll
        for (int r = 0; r < 8; r++) {
            float4 p0 = *(const float4*)&part[0][r][cg * 4];
            float4 p1 = *(const float4*)&part[1][r][cg * 4];
            float4 p2 = *(const float4*)&part[2][r][cg * 4];
            float4 v;
            v.x = acc[r].x + p0.x + p1.x + p2.x + bv.x;
            v.y = acc[r].y + p0.y + p1.y + p2.y + bv.y;
            v.z = acc[r].z + p0.z + p1.z + p2.z + bv.z;
            v.w = acc[r].w + p0.w + p1.w + p2.w + bv.w;
            *(float4*)(out + (row0 + r) * LL + colbase + cg * 4) = v;
        }
    }
}

// ============================================================
extern "C" void kernel_launch(void* const* d_in, const int* in_sizes, int n_in,
                              void* d_out, int out_size)
{
    const float* x      = (const float*)d_in[0];
    const float* a      = (const float*)d_in[1];
    const float* e      = (const float*)d_in[2];
    const float* c1_sw  = (const float*)d_in[3];
    const float* c1_sb  = (const float*)d_in[4];
    const float* c1_aiw = (const float*)d_in[5];
    const float* c1_aib = (const float*)d_in[6];
    const float* c1_ajw = (const float*)d_in[7];
    const float* c1_ajb = (const float*)d_in[8];
    const float* c1_nw  = (const float*)d_in[9];
    const float* c1_nb  = (const float*)d_in[10];
    const float* c1_ew  = (const float*)d_in[11];
    const float* c1_eb  = (const float*)d_in[12];
    const float* c2_sw  = (const float*)d_in[13];
    const float* c2_sb  = (const float*)d_in[14];
    const float* c2_aiw = (const float*)d_in[15];
    const float* c2_aib = (const float*)d_in[16];
    const float* c2_ajw = (const float*)d_in[17];
    const float* c2_ajb = (const float*)d_in[18];
    const float* c2_nw  = (const float*)d_in[19];
    const float* c2_nb  = (const float*)d_in[20];
    const float* c2_ew  = (const float*)d_in[21];
    const float* c2_eb  = (const float*)d_in[22];
    const float* dw     = (const float*)d_in[23];
    const float* db     = (const float*)d_in[24];
    float* out = (float*)d_out;

    // ---- prep: transpose a, e ----
    prep_kernel<<<dim3(169, 2), 256>>>(a, e);

    // ---- layer 1 ----
    xw_kernel<<<NN / 4, 1024>>>(x, c1_sw, c1_sb, 0);
    pair_kernel<1><<<2 * NN, 128>>>(e, a, c1_sw, c1_aiw, c1_aib, c1_ajw, c1_ajb,
                                    c1_ew, c1_eb);
    node_kernel<<<NN / 4, 512>>>(x, c1_nw, c1_nb, 1);

    // ---- layer 2 ----
    xw_kernel<<<NN / 4, 1024>>>(nullptr, c2_sw, c2_sb, 1);
    pair_kernel<2><<<2 * NN, 128>>>(nullptr, a, c2_sw, c2_aiw, c2_aib, c2_ajw, c2_ajb,
                                    c2_ew, c2_eb);
    node_kernel<<<NN / 4, 512>>>(nullptr, c2_nw, c2_nb, 2);

    // ---- readout ----
    out_kernel<<<dim3(6, NN / 8), 256>>>(dw, db, out);
}

// round 5
// speedup vs baseline: 1.1879x; 1.1879x over previous
#include <cuda_runtime.h>

#define NN 400
#define FF 240
#define CC 32
#define LL 1440
#define NK 304
#define SIN_X2 480   // row index of swE in sw; swEt at 481
#define PSTRIDE 36   // padded row stride for staged table (bank-conflict-free)

// ---- scratch (device globals; no allocation allowed) ----
__device__ float g_Xi[NN * CC];
__device__ float g_Xj[NN * CC];
__device__ float g_aggI[NN * CC];
__device__ float g_aggJ[NN * CC];
__device__ float g_e1[NN * NN];
__device__ float g_e1T[NN * NN];
__device__ float g_aT[NN * NN];
__device__ float g_eT[NN * NN];
__device__ float g_x1[NN * FF];
__device__ float g_x2[NN * FF];

// ============================================================
// K1: fused launch. blocks [0,100): xw layer1 (Xi/Xj from input x)
//                  blocks [100,185): transpose tiles (a->aT, e->eT)
// 1024 threads.
// ============================================================
__global__ void __launch_bounds__(1024) prep_xw_kernel(
    const float* __restrict__ x, const float* __restrict__ sw,
    const float* __restrict__ sb,
    const float* __restrict__ a, const float* __restrict__ e)
{
    __shared__ __align__(16) float sx[4][FF];
    __shared__ float part[4][8][CC];
    __shared__ float tbuf[4][32][33];
    int tid = threadIdx.x;

    if (blockIdx.x < 100) {
        // ---- xw layer 1 ----
        int row0 = blockIdx.x * 4;
        for (int idx = tid; idx < 4 * FF; idx += 1024)
            sx[idx / FF][idx % FF] = x[row0 * FF + idx];
        __syncthreads();

        int kq = tid >> 8;
        int t2 = tid & 255;
        int w = t2 >> 5, c = t2 & 31;
        int r = w & 3;
        bool isJ = (w >= 4);
        const float* wb = sw + (isJ ? FF * CC : 0) + c + kq * 60 * CC;
        float a0 = 0.f, a1 = 0.f, a2 = 0.f, a3 = 0.f;
        const float4* sxr = (const float4*)sx[r] + kq * 15;
#pragma unroll
        for (int f4 = 0; f4 < 15; f4++) {
            float4 xv = sxr[f4];
            int f = f4 * 4;
            a0 += xv.x * __ldg(wb + (f + 0) * CC);
            a1 += xv.y * __ldg(wb + (f + 1) * CC);
            a2 += xv.z * __ldg(wb + (f + 2) * CC);
            a3 += xv.w * __ldg(wb + (f + 3) * CC);
        }
        part[kq][w][c] = (a0 + a1) + (a2 + a3);
        __syncthreads();
        if (kq == 0) {
            float v = (part[0][w][c] + part[1][w][c]) + (part[2][w][c] + part[3][w][c]);
            if (!isJ) v += sb[c];
            (isJ ? g_Xj : g_Xi)[(row0 + r) * CC + c] = v;
        }
    } else {
        // ---- transpose: 4 tiles of 32x32 per block ----
        int sub = tid >> 8;
        int t2 = tid & 255;
        int tile = (blockIdx.x - 100) * 4 + sub;
        int tx = t2 & 31, ty = t2 >> 5;
        bool valid = (tile < 338);
        const float* src = nullptr;
        float* dst = nullptr;
        int x0 = 0, y0 = 0;
        if (valid) {
            bool isE = (tile >= 169);
            int tIdx = isE ? tile - 169 : tile;
            src = isE ? e : a;
            dst = isE ? g_eT : g_aT;
            x0 = (tIdx % 13) * 32;
            y0 = (tIdx / 13) * 32;
#pragma unroll
            for (int r = 0; r < 32; r += 8) {
                int y = y0 + ty + r, xx = x0 + tx;
                if (y < NN && xx < NN) tbuf[sub][ty + r][tx] = src[y * NN + xx];
            }
        }
        __syncthreads();
        if (valid) {
#pragma unroll
            for (int r = 0; r < 32; r += 8) {
                int y = x0 + ty + r, xx = y0 + tx;
                if (y < NN && xx < NN) dst[y * NN + xx] = tbuf[sub][tx][ty + r];
            }
        }
    }
}

// ============================================================
// K2: per-pair kernel, 2 fixed nodes per block (same mode).
// Grid 400: blocks [0,200) row mode, [200,400) col mode.
// The 400x32 Xi/Xj table is staged into padded dynamic smem
// (stride 36 -> conflict-free LDS.128); reduction aliases it.
// ============================================================
template <int LAYER>
__global__ void __launch_bounds__(256) pair_kernel(
    const float* __restrict__ eParam, const float* __restrict__ a,
    const float* __restrict__ sw,
    const float* __restrict__ aiw, const float* __restrict__ aib,
    const float* __restrict__ ajw, const float* __restrict__ ajb,
    const float* __restrict__ ew,  const float* __restrict__ eb)
{
    extern __shared__ float dyn[];   // [400*36] staging, aliased as sAcc[256][33]
    __shared__ __align__(16) float4 q[2][CC];
    __shared__ float sEw[CC];
    __shared__ float sPart[8][CC];

    const float* e  = (LAYER == 2) ? g_e1  : eParam;
    const float* eT = (LAYER == 2) ? g_e1T : g_eT;
    bool colMode = (blockIdx.x >= 200);
    int fixedBase = (colMode ? (blockIdx.x - 200) : blockIdx.x) * 2;

    int tid = threadIdx.x;
    int grp = tid >> 7;          // 0 or 1
    int t128 = tid & 127;
    int fixed = fixedBase + grp;

    // stage the varying-node table into padded smem (coalesced)
    const float4* srcX = (const float4*)(colMode ? g_Xi : g_Xj);
    for (int i = tid; i < NN * (CC / 4); i += 256) {
        int v = i >> 3, c4 = i & 7;
        ((float4*)(dyn + v * PSTRIDE))[c4] = srcX[i];
    }
    if (tid < 2 * CC) {
        int g = tid >> 5, c = tid & 31;
        int fx = fixedBase + g;
        float fv = colMode ? g_Xj[fx * CC + c] : g_Xi[fx * CC + c];
        float gw = colMode ? ajw[c] : aiw[c];
        q[g][c] = make_float4(fv, sw[SIN_X2 * CC + c], sw[(SIN_X2 + 1) * CC + c], gw);
        if (LAYER == 1 && g == 0) sEw[c] = ew[c];
    }
    __syncthreads();

    const float* pA   = (colMode ? eT : e)  + fixed * NN;
    const float* pB   = (colMode ? e  : eT) + fixed * NN;
    const float* pAdj = (colMode ? g_aT : a) + fixed * NN;
    float gb  = colMode ? ajb[0] : aib[0];
    float ebv = (LAYER == 1) ? eb[0] : 0.f;
    float* eOut = (colMode ? g_e1T : g_e1) + fixed * NN;

    float acc[CC];
#pragma unroll
    for (int c = 0; c < CC; c++) acc[c] = 0.f;

    for (int v = t128; v < NN; v += 128) {
        float eij = __ldg(pA + v);
        float eji = __ldg(pB + v);
        float av  = __ldg(pAdj + v);
        const float4* vr = (const float4*)(dyn + v * PSTRIDE);

        float s = 0.f, se = 0.f;
        float tv[CC];
#pragma unroll
        for (int c4 = 0; c4 < CC / 4; c4++) {
            float4 vv = vr[c4];
            float vvals[4] = {vv.x, vv.y, vv.z, vv.w};
#pragma unroll
            for (int u = 0; u < 4; u++) {
                int c = c4 * 4 + u;
                float4 qq = q[grp][c];
                float t = qq.x + vvals[u] + eij * qq.y + eji * qq.z;
                t = fmaxf(t, 0.f) * av;
                tv[c] = t;
                s += t * qq.w;
                if (LAYER == 1) se += t * sEw[c];
            }
        }
        float gate = 1.f / (1.f + __expf(-(s + gb)));
#pragma unroll
        for (int c = 0; c < CC; c++) acc[c] += gate * tv[c];
        if (LAYER == 1) eOut[v] = se + ebv;
    }

    __syncthreads();   // staging table no longer needed; alias as sAcc
    float* sAcc = dyn; // [256][33]
#pragma unroll
    for (int c = 0; c < CC; c++) sAcc[tid * 33 + c] = acc[c];
    __syncthreads();
    {
        int w2 = t128 >> 5, c = t128 & 31;
        int rowbase = grp * 128 + w2 * 32;
        float p = 0.f;
#pragma unroll
        for (int k = 0; k < 32; k++) p += sAcc[(rowbase + k) * 33 + c];
        sPart[grp * 4 + w2][c] = p;
    }
    __syncthreads();
    if (tid < 2 * CC) {
        int g = tid >> 5, c = tid & 31;
        float r = (sPart[g * 4 + 0][c] + sPart[g * 4 + 1][c]) +
                  (sPart[g * 4 + 2][c] + sPart[g * 4 + 3][c]);
        (colMode ? g_aggJ : g_aggI)[(fixedBase + g) * CC + c] = r;
    }
}

// ============================================================
// K3: node model  x_out = [x, aggI, aggJ] @ nw + nb  (K=304)
// R3 structure: 1024 thr, 4 K-quarters(76), f = tid&255 (<240).
// LAYER 1 additionally computes Xi/Xj for layer 2 (fused xw2).
// ============================================================
template <int LAYER>
__global__ void __launch_bounds__(1024) node_kernel(
    const float* __restrict__ xin, const float* __restrict__ nw,
    const float* __restrict__ nb,
    const float* __restrict__ sw2, const float* __restrict__ sb2)
{
    const float* x = (LAYER == 1) ? xin : g_x1;
    float* xout = (LAYER == 1) ? g_x1 : g_x2;
    __shared__ __align__(16) float s[4][NK];
    __shared__ float part[4][4][FF];
    __shared__ float sx1[4][FF];
    int row0 = blockIdx.x * 4;
    int tid = threadIdx.x;
    for (int idx = tid; idx < 4 * NK; idx += 1024) {
        int r = idx / NK, k = idx % NK;
        float v;
        if (k < FF)            v = x[(row0 + r) * FF + k];
        else if (k < FF + CC)  v = g_aggI[(row0 + r) * CC + (k - FF)];
        else                   v = g_aggJ[(row0 + r) * CC + (k - FF - CC)];
        s[r][k] = v;
    }
    __syncthreads();

    int kq = tid >> 8;
    int f = tid & 255;
    if (f < FF) {
        const float* wp = nw + f;
        float a0 = 0.f, a1 = 0.f, a2 = 0.f, a3 = 0.f;
#pragma unroll
        for (int k4 = 0; k4 < 19; k4++) {
            int k = kq * 76 + k4 * 4;
            float w0 = __ldg(wp + (k + 0) * FF);
            float w1 = __ldg(wp + (k + 1) * FF);
            float w2 = __ldg(wp + (k + 2) * FF);
            float w3 = __ldg(wp + (k + 3) * FF);
            float4 x0 = *(const float4*)&s[0][k];
            float4 x1 = *(const float4*)&s[1][k];
            float4 x2 = *(const float4*)&s[2][k];
            float4 x3 = *(const float4*)&s[3][k];
            a0 += x0.x * w0 + x0.y * w1 + x0.z * w2 + x0.w * w3;
            a1 += x1.x * w0 + x1.y * w1 + x1.z * w2 + x1.w * w3;
            a2 += x2.x * w0 + x2.y * w1 + x2.z * w2 + x2.w * w3;
            a3 += x3.x * w0 + x3.y * w1 + x3.z * w2 + x3.w * w3;
        }
        part[kq][0][f] = a0;
        part[kq][1][f] = a1;
        part[kq][2][f] = a2;
        part[kq][3][f] = a3;
    }
    __syncthreads();
    for (int idx = tid; idx < 4 * FF; idx += 1024) {
        int r = idx / FF, f2 = idx % FF;
        float v = (part[0][r][f2] + part[1][r][f2]) +
                  (part[2][r][f2] + part[3][r][f2]) + nb[f2];
        xout[(row0 + r) * FF + f2] = v;
        if (LAYER == 1) sx1[r][f2] = v;
    }

    if (LAYER == 1) {
        // fused xw for layer 2: Xi/Xj = x1 @ sw2 (+ sb2 for Xi)
        __syncthreads();
        int t2 = tid & 255;
        int r = t2 >> 6, c = t2 & 63;
        const float* wq = sw2 + ((c < 32) ? 0 : FF * CC) + (c & 31);
        float acc = 0.f;
#pragma unroll 4
        for (int k = 0; k < 60; k++) {
            int kk = kq * 60 + k;
            acc += sx1[r][kk] * __ldg(wq + kk * CC);
        }
        part[kq][r][c] = acc;   // reuse (safe: after sync)
        __syncthreads();
        if (kq == 0) {
            float v = (part[0][r][c] + part[1][r][c]) +
                      (part[2][r][c] + part[3][r][c]);
            if (c < 32) g_Xi[(row0 + r) * CC + c] = v + sb2[c];
            else        g_Xj[(row0 + r) * CC + (c - 32)] = v;
        }
    }
}

// ============================================================
// K4: out = x2 @ dw + db   (400 x 1440, K=240)
// 256 thr = 4 K-quarters(60) x 64 (60 active colgroups x 4 cols).
// 8 rows x 240 cols per block; grid (6, 50).
// ============================================================
__global__ void __launch_bounds__(256) out_kernel(
    const float* __restrict__ dw, const float* __restrict__ db,
    float* __restrict__ out)
{
    __shared__ float s[8][FF];
    __shared__ float part[3][8][240];
    int tid = threadIdx.x;
    int row0 = blockIdx.y * 8;
    int colbase = blockIdx.x * 240;
    for (int idx = tid; idx < 8 * FF; idx += 256)
        s[idx / FF][idx % FF] = g_x2[row0 * FF + idx];
    __syncthreads();

    int kq = tid >> 6, cg = tid & 63;
    float4 acc[8];
#pragma unroll
    for (int r = 0; r < 8; r++) acc[r] = make_float4(0.f, 0.f, 0.f, 0.f);

    if (cg < 60) {
        const float* wp = dw + colbase + cg * 4;
        int kbase = kq * 60;
#pragma unroll 4
        for (int kk = 0; kk < 60; kk++) {
            int k = kbase + kk;
            float4 w = *(const float4*)(wp + k * LL);
#pragma unroll
            for (int r = 0; r < 8; r++) {
                float xr = s[r][k];
                acc[r].x += xr * w.x;
                acc[r].y += xr * w.y;
                acc[r].z += xr * w.z;
                acc[r].w += xr * w.w;
            }
        }
        if (kq > 0) {
#pragma unroll
            for (int r = 0; r < 8; r++)
                *(float4*)&part[kq - 1][r][cg * 4] = acc[r];
        }
    }
    __syncthreads();
    if (kq == 0 && cg < 60) {
        float4 bv = *(const float4*)(db + colbase + cg * 4);
#pragma unroll
        for (int r = 0; r < 8; r++) {
            float4 p0 = *(const float4*)&part[0][r][cg * 4];
            float4 p1 = *(const float4*)&part[1][r][cg * 4];
            float4 p2 = *(const float4*)&part[2][r][cg * 4];
            float4 v;
            v.x = acc[r].x + p0.x + p1.x + p2.x + bv.x;
            v.y = acc[r].y + p0.y + p1.y + p2.y + bv.y;
            v.z = acc[r].z + p0.z + p1.z + p2.z + bv.z;
            v.w = acc[r].w + p0.w + p1.w + p2.w + bv.w;
            *(float4*)(out + (row0 + r) * LL + colbase + cg * 4) = v;
        }
    }
}

// ============================================================
extern "C" void kernel_launch(void* const* d_in, const int* in_sizes, int n_in,
                              void* d_out, int out_size)
{
    const float* x      = (const float*)d_in[0];
    const float* a      = (const float*)d_in[1];
    const float* e      = (const float*)d_in[2];
    const float* c1_sw  = (const float*)d_in[3];
    const float* c1_sb  = (const float*)d_in[4];
    const float* c1_aiw = (const float*)d_in[5];
    const float* c1_aib = (const float*)d_in[6];
    const float* c1_ajw = (const float*)d_in[7];
    const float* c1_ajb = (const float*)d_in[8];
    const float* c1_nw  = (const float*)d_in[9];
    const float* c1_nb  = (const float*)d_in[10];
    const float* c1_ew  = (const float*)d_in[11];
    const float* c1_eb  = (const float*)d_in[12];
    const float* c2_sw  = (const float*)d_in[13];
    const float* c2_sb  = (const float*)d_in[14];
    const float* c2_aiw = (const float*)d_in[15];
    const float* c2_aib = (const float*)d_in[16];
    const float* c2_ajw = (const float*)d_in[17];
    const float* c2_ajb = (const float*)d_in[18];
    const float* c2_nw  = (const float*)d_in[19];
    const float* c2_nb  = (const float*)d_in[20];
    const float* c2_ew  = (const float*)d_in[21];
    const float* c2_eb  = (const float*)d_in[22];
    const float* dw     = (const float*)d_in[23];
    const float* db     = (const float*)d_in[24];
    float* out = (float*)d_out;

    const int DYN = NN * PSTRIDE * sizeof(float);   // 57600 B
    static bool attrDone = false;
    if (!attrDone) {
        cudaFuncSetAttribute(pair_kernel<1>, cudaFuncAttributeMaxDynamicSharedMemorySize, DYN);
        cudaFuncSetAttribute(pair_kernel<2>, cudaFuncAttributeMaxDynamicSharedMemorySize, DYN);
        attrDone = true;
    }

    // ---- layer 1 (xw + transposes fused in one launch) ----
    prep_xw_kernel<<<185, 1024>>>(x, c1_sw, c1_sb, a, e);
    pair_kernel<1><<<400, 256, DYN>>>(e, a, c1_sw, c1_aiw, c1_aib, c1_ajw, c1_ajb,
                                      c1_ew, c1_eb);
    node_kernel<1><<<NN / 4, 1024>>>(x, c1_nw, c1_nb, c2_sw, c2_sb);

    // ---- layer 2 (Xi/Xj already produced by node_kernel<1>) ----
    pair_kernel<2><<<400, 256, DYN>>>(nullptr, a, c2_sw, c2_aiw, c2_aib, c2_ajw, c2_ajb,
                                      c2_ew, c2_eb);
    node_kernel<2><<<NN / 4, 1024>>>(nullptr, c2_nw, c2_nb, nullptr, nullptr);

    // ---- readout ----
    out_kernel<<<dim3(6, NN / 8), 256>>>(dw, db, out);
}

// round 6
// speedup vs baseline: 1.3233x; 1.1140x over previous
#include <cuda_runtime.h>

#define NN 400
#define FF 240
#define CC 32
#define LL 1440
#define NK 304
#define SIN_X2 480   // row index of swE in sw; swEt at 481

// ---- scratch (device globals; no allocation allowed) ----
__device__ float g_XiT[CC * NN];   // transposed: [c][node]
__device__ float g_XjT[CC * NN];
__device__ float g_aggI[NN * CC];
__device__ float g_aggJ[NN * CC];
__device__ float g_e1[NN * NN];
__device__ float g_e1T[NN * NN];
__device__ float g_aT[NN * NN];
__device__ float g_eT[NN * NN];
__device__ float g_x1[NN * FF];
__device__ float g_x2[NN * FF];

// ============================================================
// K1: fused launch. blocks [0,100): xw layer1 (XiT/XjT from input x)
//                  blocks [100,185): transpose tiles (a->aT, e->eT)
// ============================================================
__global__ void __launch_bounds__(1024) prep_xw_kernel(
    const float* __restrict__ x, const float* __restrict__ sw,
    const float* __restrict__ sb,
    const float* __restrict__ a, const float* __restrict__ e)
{
    __shared__ __align__(16) float sx[4][FF];
    __shared__ float part[4][8][CC];
    __shared__ float tbuf[4][32][33];
    int tid = threadIdx.x;

    if (blockIdx.x < 100) {
        int row0 = blockIdx.x * 4;
        for (int idx = tid; idx < 4 * FF; idx += 1024)
            sx[idx / FF][idx % FF] = x[row0 * FF + idx];
        __syncthreads();

        int kq = tid >> 8;
        int t2 = tid & 255;
        int w = t2 >> 5, c = t2 & 31;
        int r = w & 3;
        bool isJ = (w >= 4);
        const float* wb = sw + (isJ ? FF * CC : 0) + c + kq * 60 * CC;
        float a0 = 0.f, a1 = 0.f, a2 = 0.f, a3 = 0.f;
        const float4* sxr = (const float4*)sx[r] + kq * 15;
#pragma unroll
        for (int f4 = 0; f4 < 15; f4++) {
            float4 xv = sxr[f4];
            int f = f4 * 4;
            a0 += xv.x * __ldg(wb + (f + 0) * CC);
            a1 += xv.y * __ldg(wb + (f + 1) * CC);
            a2 += xv.z * __ldg(wb + (f + 2) * CC);
            a3 += xv.w * __ldg(wb + (f + 3) * CC);
        }
        part[kq][w][c] = (a0 + a1) + (a2 + a3);
        __syncthreads();
        if (kq == 0) {
            float v = (part[0][w][c] + part[1][w][c]) + (part[2][w][c] + part[3][w][c]);
            if (!isJ) v += sb[c];
            (isJ ? g_XjT : g_XiT)[c * NN + row0 + r] = v;
        }
    } else {
        int sub = tid >> 8;
        int t2 = tid & 255;
        int tile = (blockIdx.x - 100) * 4 + sub;
        int tx = t2 & 31, ty = t2 >> 5;
        bool valid = (tile < 338);
        const float* src = nullptr;
        float* dst = nullptr;
        int x0 = 0, y0 = 0;
        if (valid) {
            bool isE = (tile >= 169);
            int tIdx = isE ? tile - 169 : tile;
            src = isE ? e : a;
            dst = isE ? g_eT : g_aT;
            x0 = (tIdx % 13) * 32;
            y0 = (tIdx / 13) * 32;
#pragma unroll
            for (int r = 0; r < 32; r += 8) {
                int y = y0 + ty + r, xx = x0 + tx;
                if (y < NN && xx < NN) tbuf[sub][ty + r][tx] = src[y * NN + xx];
            }
        }
        __syncthreads();
        if (valid) {
#pragma unroll
            for (int r = 0; r < 32; r += 8) {
                int y = x0 + ty + r, xx = y0 + tx;
                if (y < NN && xx < NN) dst[y * NN + xx] = tbuf[sub][tx][ty + r];
            }
        }
    }
}

// ============================================================
// K2: per-pair kernel. Grid 400: [0,200) row mode, [200,400) col.
// 2 fixed nodes per block (grp = tid>>7). Within 128 threads:
//   vg = (t&127)>>1 owns node v (strides 64), half = t&1 owns
//   channels [half*16, half*16+16). Lane-pair shuffle finishes the
//   gate/edge dots. Varying-node features come from transposed
//   XiT/XjT in gmem (L1-resident, coalesced).
// ============================================================
template <int LAYER>
__global__ void __launch_bounds__(256) pair_kernel(
    const float* __restrict__ eParam, const float* __restrict__ a,
    const float* __restrict__ sw,
    const float* __restrict__ aiw, const float* __restrict__ aib,
    const float* __restrict__ ajw, const float* __restrict__ ajb,
    const float* __restrict__ ew,  const float* __restrict__ eb)
{
    __shared__ __align__(16) float4 q[2][CC];
    __shared__ float sEw[CC];
    __shared__ float sRed[64][68];

    const float* e  = (LAYER == 2) ? g_e1  : eParam;
    const float* eT = (LAYER == 2) ? g_e1T : g_eT;
    bool colMode = (blockIdx.x >= 200);
    int fixedBase = (colMode ? (blockIdx.x - 200) : blockIdx.x) * 2;

    int tid = threadIdx.x;
    int grp = tid >> 7;
    int t128 = tid & 127;
    int vg = t128 >> 1;
    int half = t128 & 1;
    int fixed = fixedBase + grp;

    if (tid < 2 * CC) {
        int g = tid >> 5, c = tid & 31;
        int fx = fixedBase + g;
        float fv = (colMode ? g_XjT : g_XiT)[c * NN + fx];
        float gw = colMode ? ajw[c] : aiw[c];
        q[g][c] = make_float4(fv, sw[SIN_X2 * CC + c], sw[(SIN_X2 + 1) * CC + c], gw);
        if (LAYER == 1 && g == 0) sEw[c] = ew[c];
    }
    __syncthreads();

    const float* xT   = colMode ? g_XiT : g_XjT;   // varying-node table
    const float* pA   = (colMode ? eT : e)  + fixed * NN;
    const float* pB   = (colMode ? e  : eT) + fixed * NN;
    const float* pAdj = (colMode ? g_aT : a) + fixed * NN;
    float gb  = colMode ? ajb[0] : aib[0];
    float ebv = (LAYER == 1) ? eb[0] : 0.f;
    float* eOut = (colMode ? g_e1T : g_e1) + fixed * NN;

    const float4* qh = &q[grp][half * 16];
    const float*  eh = &sEw[half * 16];
    const float*  xh = xT + (half * 16) * NN;

    float acc[16];
#pragma unroll
    for (int c = 0; c < 16; c++) acc[c] = 0.f;

    for (int v = vg; v < NN; v += 64) {
        float eij = __ldg(pA + v);
        float eji = __ldg(pB + v);
        float av  = __ldg(pAdj + v);

        float s = 0.f, se = 0.f;
        float tv[16];
#pragma unroll
        for (int c = 0; c < 16; c++) {
            float vv = __ldg(xh + c * NN + v);
            float4 qq = qh[c];
            float t = qq.x + vv + eij * qq.y + eji * qq.z;
            t = fmaxf(t, 0.f) * av;
            tv[c] = t;
            s += t * qq.w;
            if (LAYER == 1) se += t * eh[c];
        }
        s += __shfl_xor_sync(0xffffffffu, s, 1);
        if (LAYER == 1) se += __shfl_xor_sync(0xffffffffu, se, 1);
        float gate = 1.f / (1.f + __expf(-(s + gb)));
#pragma unroll
        for (int c = 0; c < 16; c++) acc[c] += gate * tv[c];
        if (LAYER == 1 && half == 0) eOut[v] = se + ebv;
    }

    // block reduce: sRed[vg][grp*32 + half*16 + c], sum over vg
    {
        float* dstr = &sRed[vg][grp * 32 + half * 16];
#pragma unroll
        for (int c4 = 0; c4 < 4; c4++)
            *(float4*)(dstr + c4 * 4) = *(float4*)(acc + c4 * 4);
    }
    __syncthreads();
    if (tid < 64) {
        float p = 0.f;
#pragma unroll 8
        for (int k = 0; k < 64; k++) p += sRed[k][tid];
        int g = tid >> 5, cc = tid & 31;
        (colMode ? g_aggJ : g_aggI)[(fixedBase + g) * CC + cc] = p;
    }
}

// ============================================================
// K3: node model  x_out = [x, aggI, aggJ] @ nw + nb  (K=304)
// 1024 thr, 4 K-quarters(76), f = tid&255 (<240).
// LAYER 1 additionally computes XiT/XjT for layer 2 (fused xw2).
// ============================================================
template <int LAYER>
__global__ void __launch_bounds__(1024) node_kernel(
    const float* __restrict__ xin, const float* __restrict__ nw,
    const float* __restrict__ nb,
    const float* __restrict__ sw2, const float* __restrict__ sb2)
{
    const float* x = (LAYER == 1) ? xin : g_x1;
    float* xout = (LAYER == 1) ? g_x1 : g_x2;
    __shared__ __align__(16) float s[4][NK];
    __shared__ float part[4][4][FF];
    __shared__ float sx1[4][FF];
    int row0 = blockIdx.x * 4;
    int tid = threadIdx.x;
    for (int idx = tid; idx < 4 * NK; idx += 1024) {
        int r = idx / NK, k = idx % NK;
        float v;
        if (k < FF)            v = x[(row0 + r) * FF + k];
        else if (k < FF + CC)  v = g_aggI[(row0 + r) * CC + (k - FF)];
        else                   v = g_aggJ[(row0 + r) * CC + (k - FF - CC)];
        s[r][k] = v;
    }
    __syncthreads();

    int kq = tid >> 8;
    int f = tid & 255;
    if (f < FF) {
        const float* wp = nw + f;
        float a0 = 0.f, a1 = 0.f, a2 = 0.f, a3 = 0.f;
#pragma unroll
        for (int k4 = 0; k4 < 19; k4++) {
            int k = kq * 76 + k4 * 4;
            float w0 = __ldg(wp + (k + 0) * FF);
            float w1 = __ldg(wp + (k + 1) * FF);
            float w2 = __ldg(wp + (k + 2) * FF);
            float w3 = __ldg(wp + (k + 3) * FF);
            float4 x0 = *(const float4*)&s[0][k];
            float4 x1 = *(const float4*)&s[1][k];
            float4 x2 = *(const float4*)&s[2][k];
            float4 x3 = *(const float4*)&s[3][k];
            a0 += x0.x * w0 + x0.y * w1 + x0.z * w2 + x0.w * w3;
            a1 += x1.x * w0 + x1.y * w1 + x1.z * w2 + x1.w * w3;
            a2 += x2.x * w0 + x2.y * w1 + x2.z * w2 + x2.w * w3;
            a3 += x3.x * w0 + x3.y * w1 + x3.z * w2 + x3.w * w3;
        }
        part[kq][0][f] = a0;
        part[kq][1][f] = a1;
        part[kq][2][f] = a2;
        part[kq][3][f] = a3;
    }
    __syncthreads();
    for (int idx = tid; idx < 4 * FF; idx += 1024) {
        int r = idx / FF, f2 = idx % FF;
        float v = (part[0][r][f2] + part[1][r][f2]) +
                  (part[2][r][f2] + part[3][r][f2]) + nb[f2];
        xout[(row0 + r) * FF + f2] = v;
        if (LAYER == 1) sx1[r][f2] = v;
    }

    if (LAYER == 1) {
        // fused xw for layer 2: XiT/XjT = (x1 @ sw2)^T (+ sb2 for Xi)
        __syncthreads();
        int t2 = tid & 255;
        int r = t2 >> 6, c = t2 & 63;
        const float* wq = sw2 + ((c < 32) ? 0 : FF * CC) + (c & 31);
        float acc = 0.f;
#pragma unroll 4
        for (int k = 0; k < 60; k++) {
            int kk = kq * 60 + k;
            acc += sx1[r][kk] * __ldg(wq + kk * CC);
        }
        part[kq][r][c] = acc;
        __syncthreads();
        if (kq == 0) {
            float v = (part[0][r][c] + part[1][r][c]) +
                      (part[2][r][c] + part[3][r][c]);
            if (c < 32) g_XiT[c * NN + row0 + r] = v + sb2[c];
            else        g_XjT[(c - 32) * NN + row0 + r] = v;
        }
    }
}

// ============================================================
// K4: out = x2 @ dw + db   (400 x 1440, K=240)
// ============================================================
__global__ void __launch_bounds__(256) out_kernel(
    const float* __restrict__ dw, const float* __restrict__ db,
    float* __restrict__ out)
{
    __shared__ float s[8][FF];
    __shared__ float part[3][8][240];
    int tid = threadIdx.x;
    int row0 = blockIdx.y * 8;
    int colbase = blockIdx.x * 240;
    for (int idx = tid; idx < 8 * FF; idx += 256)
        s[idx / FF][idx % FF] = g_x2[row0 * FF + idx];
    __syncthreads();

    int kq = tid >> 6, cg = tid & 63;
    float4 acc[8];
#pragma unroll
    for (int r = 0; r < 8; r++) acc[r] = make_float4(0.f, 0.f, 0.f, 0.f);

    if (cg < 60) {
        const float* wp = dw + colbase + cg * 4;
        int kbase = kq * 60;
#pragma unroll 4
        for (int kk = 0; kk < 60; kk++) {
            int k = kbase + kk;
            float4 w = *(const float4*)(wp + k * LL);
#pragma unroll
            for (int r = 0; r < 8; r++) {
                float xr = s[r][k];
                acc[r].x += xr * w.x;
                acc[r].y += xr * w.y;
                acc[r].z += xr * w.z;
                acc[r].w += xr * w.w;
            }
        }
        if (kq > 0) {
#pragma unroll
            for (int r = 0; r < 8; r++)
                *(float4*)&part[kq - 1][r][cg * 4] = acc[r];
        }
    }
    __syncthreads();
    if (kq == 0 && cg < 60) {
        float4 bv = *(const float4*)(db + colbase + cg * 4);
#pragma unroll
        for (int r = 0; r < 8; r++) {
            float4 p0 = *(const float4*)&part[0][r][cg * 4];
            float4 p1 = *(const float4*)&part[1][r][cg * 4];
            float4 p2 = *(const float4*)&part[2][r][cg * 4];
            float4 v;
            v.x = acc[r].x + p0.x + p1.x + p2.x + bv.x;
            v.y = acc[r].y + p0.y + p1.y + p2.y + bv.y;
            v.z = acc[r].z + p0.z + p1.z + p2.z + bv.z;
            v.w = acc[r].w + p0.w + p1.w + p2.w + bv.w;
            *(float4*)(out + (row0 + r) * LL + colbase + cg * 4) = v;
        }
    }
}

// ============================================================
extern "C" void kernel_launch(void* const* d_in, const int* in_sizes, int n_in,
                              void* d_out, int out_size)
{
    const float* x      = (const float*)d_in[0];
    const float* a      = (const float*)d_in[1];
    const float* e      = (const float*)d_in[2];
    const float* c1_sw  = (const float*)d_in[3];
    const float* c1_sb  = (const float*)d_in[4];
    const float* c1_aiw = (const float*)d_in[5];
    const float* c1_aib = (const float*)d_in[6];
    const float* c1_ajw = (const float*)d_in[7];
    const float* c1_ajb = (const float*)d_in[8];
    const float* c1_nw  = (const float*)d_in[9];
    const float* c1_nb  = (const float*)d_in[10];
    const float* c1_ew  = (const float*)d_in[11];
    const float* c1_eb  = (const float*)d_in[12];
    const float* c2_sw  = (const float*)d_in[13];
    const float* c2_sb  = (const float*)d_in[14];
    const float* c2_aiw = (const float*)d_in[15];
    const float* c2_aib = (const float*)d_in[16];
    const float* c2_ajw = (const float*)d_in[17];
    const float* c2_ajb = (const float*)d_in[18];
    const float* c2_nw  = (const float*)d_in[19];
    const float* c2_nb  = (const float*)d_in[20];
    const float* c2_ew  = (const float*)d_in[21];
    const float* c2_eb  = (const float*)d_in[22];
    const float* dw     = (const float*)d_in[23];
    const float* db     = (const float*)d_in[24];
    float* out = (float*)d_out;

    // ---- layer 1 (xw + transposes fused in one launch) ----
    prep_xw_kernel<<<185, 1024>>>(x, c1_sw, c1_sb, a, e);
    pair_kernel<1><<<400, 256>>>(e, a, c1_sw, c1_aiw, c1_aib, c1_ajw, c1_ajb,
                                 c1_ew, c1_eb);
    node_kernel<1><<<NN / 4, 1024>>>(x, c1_nw, c1_nb, c2_sw, c2_sb);

    // ---- layer 2 (XiT/XjT already produced by node_kernel<1>) ----
    pair_kernel<2><<<400, 256>>>(nullptr, a, c2_sw, c2_aiw, c2_aib, c2_ajw, c2_ajb,
                                 c2_ew, c2_eb);
    node_kernel<2><<<NN / 4, 1024>>>(nullptr, c2_nw, c2_nb, nullptr, nullptr);

    // ---- readout ----
    out_kernel<<<dim3(6, NN / 8), 256>>>(dw, db, out);
}